// round 1
// baseline (speedup 1.0000x reference)
#include <cuda_runtime.h>

// PatchGram: per sample n, per layer:
//   f[cr][p]  = mean over K=C/64 consecutive channels of feat[n, cr*K+j, p]   (p in [0,9))
//   g[d4][p]  = sum over 4 consecutive cr rows of f                            (d4 in [0,16))
//   out[n, layer, c*16+d4] = (1/36) * sum_p f[c][p] * g[d4][p]
// (Gram/9 followed by pool-4 over the flattened 64x64 Gram collapses to the above,
//  since each pool-4 group stays inside one Gram row.)

template <int C>
__global__ __launch_bounds__(256, 1)
void patch_gram_kernel(const float* __restrict__ feat,
                       float* __restrict__ out,
                       int layer)
{
    constexpr int K     = C / 64;      // channels per pooled group (8 or 16)
    constexpr int ELEMS = C * 9;       // floats per sample tile

    __shared__ float tile[ELEMS];      // staged input tile
    __shared__ float f[64 * 9];        // channel-reduced features
    __shared__ float g[16 * 9];        // 4-row group sums of f

    const int n   = blockIdx.x;
    const int tid = threadIdx.x;

    // ---- Stage 1: coalesced float4 load of the whole per-sample tile ----
    {
        const float4* __restrict__ src = reinterpret_cast<const float4*>(feat + (size_t)n * ELEMS);
        float4* dst = reinterpret_cast<float4*>(tile);
        #pragma unroll
        for (int i = tid; i < ELEMS / 4; i += 256) {
            dst[i] = src[i];
        }
    }
    __syncthreads();

    // ---- Stage 2: channel pooling C -> 64 (mean over K consecutive channels) ----
    {
        constexpr float inv_k = 1.0f / (float)K;
        for (int i = tid; i < 576; i += 256) {   // i = cr*9 + p
            const int cr = i / 9;
            const int p  = i - cr * 9;
            const float* base = tile + (cr * K) * 9 + p;
            float s = 0.0f;
            #pragma unroll
            for (int j = 0; j < K; ++j) s += base[j * 9];
            f[i] = s * inv_k;
        }
    }
    __syncthreads();

    // ---- Stage 3: 4-row group sums (for the final pool-4 over Gram rows) ----
    if (tid < 144) {                             // tid = d4*9 + p
        const int d4 = tid / 9;
        const int p  = tid - d4 * 9;
        const float* base = f + (4 * d4) * 9 + p;
        g[tid] = base[0] + base[9] + base[18] + base[27];
    }
    __syncthreads();

    // ---- Stage 4: 64x16 output dots over p=9, coalesced store ----
    {
        float* __restrict__ dst = out + ((size_t)n * 2 + layer) * 1024;
        constexpr float scale = 1.0f / 36.0f;    // 1/P (=9) * 1/4 (pool)
        #pragma unroll
        for (int o = tid; o < 1024; o += 256) {
            const int c  = o >> 4;
            const int d4 = o & 15;
            const float* fr = f + c * 9;
            const float* gr = g + d4 * 9;
            float acc = 0.0f;
            #pragma unroll
            for (int p = 0; p < 9; ++p) acc = fmaf(fr[p], gr[p], acc);
            dst[o] = acc * scale;
        }
    }
}

extern "C" void kernel_launch(void* const* d_in, const int* in_sizes, int n_in,
                              void* d_out, int out_size)
{
    const float* feat0 = (const float*)d_in[0];   // [6272, 512, 3, 3]
    const float* feat1 = (const float*)d_in[1];   // [6272, 1024, 3, 3]
    float* out = (float*)d_out;                   // [6272, 2, 1024]

    const int N0 = in_sizes[0] / (512 * 9);
    const int N1 = in_sizes[1] / (1024 * 9);

    patch_gram_kernel<512><<<N0, 256>>>(feat0, out, 0);
    patch_gram_kernel<1024><<<N1, 256>>>(feat1, out, 1);
}